// round 17
// baseline (speedup 1.0000x reference)
#include <cuda_runtime.h>
#include <cuda_bf16.h>
#include <math.h>

#define TT 512
#define BB 256
#define DD 256
#define HH 256
#define KK 256
#define GG 1024  // 4*H

#define RBLK 128     // persistent recurrence grid: 8 batch-groups x 16 n-blocks
#define RTHR 256

// Scratch state (static device globals: allocation-free per harness rules)
__device__ float g_gx[(size_t)TT * BB * GG];   // precomputed x-path gates + biases
__device__ float g_hm[2][BB * HH];             // double-buffered (h .* mask_h)
__device__ unsigned g_bar = 0;                 // grid barrier counter
__device__ unsigned g_gen = 0;                 // grid barrier generation

// ===========================================================================
// Split helpers (R15-proven forms; sm_80+ mma.sync only — valid on sm_100a)
// ===========================================================================
__device__ __forceinline__ unsigned f2tf(float a) {
    unsigned r;
    asm("cvt.rna.tf32.f32 %0, %1;" : "=r"(r) : "f"(a));
    return r;
}
__device__ __forceinline__ void split_tf32(float a, unsigned& h, unsigned& l) {
    h = f2tf(a);
    l = f2tf(a - __uint_as_float(h));
}
__device__ __forceinline__ void mma_tf32(float* c, const unsigned* a,
                                         unsigned b0, unsigned b1) {
    asm("mma.sync.aligned.m16n8k8.row.col.f32.tf32.tf32.f32 "
        "{%0,%1,%2,%3}, {%4,%5,%6,%7}, {%8,%9}, {%0,%1,%2,%3};"
        : "+f"(c[0]), "+f"(c[1]), "+f"(c[2]), "+f"(c[3])
        : "r"(a[0]), "r"(a[1]), "r"(a[2]), "r"(a[3]), "r"(b0), "r"(b1));
}

// bf16 2-way split of a float pair, packed for m16n8k16 fragments
// (low 16 bits = even-k element, high 16 bits = odd-k element)
__device__ __forceinline__ void splitb2(float x0, float x1,
                                        unsigned& hi, unsigned& lo) {
    __nv_bfloat16 h0 = __float2bfloat16_rn(x0);
    __nv_bfloat16 h1 = __float2bfloat16_rn(x1);
    hi = ((unsigned)__bfloat16_as_ushort(h1) << 16) |
         (unsigned)__bfloat16_as_ushort(h0);
    __nv_bfloat16 l0 = __float2bfloat16_rn(x0 - __bfloat162float(h0));
    __nv_bfloat16 l1 = __float2bfloat16_rn(x1 - __bfloat162float(h1));
    lo = ((unsigned)__bfloat16_as_ushort(l1) << 16) |
         (unsigned)__bfloat16_as_ushort(l0);
}
__device__ __forceinline__ void mma_bf16(float* c, const unsigned* a,
                                         unsigned b0, unsigned b1) {
    asm("mma.sync.aligned.m16n8k16.row.col.f32.bf16.bf16.f32 "
        "{%0,%1,%2,%3}, {%4,%5,%6,%7}, {%8,%9}, {%0,%1,%2,%3};"
        : "+f"(c[0]), "+f"(c[1]), "+f"(c[2]), "+f"(c[3])
        : "r"(a[0]), "r"(a[1]), "r"(a[2]), "r"(a[3]), "r"(b0), "r"(b1));
}

// ---------------------------------------------------------------------------
// gemm_x loaders as plain inline functions (no macros)
// ---------------------------------------------------------------------------
__device__ __forceinline__ void g_load_chunk(
    const float* __restrict__ X, const float* __restrict__ MX,
    const float* __restrict__ W, int m0, int n0, int k0,
    int arow, int akq, float4* pa, float4* pb)
{
#pragma unroll
    for (int q = 0; q < 4; q++) {
        int row = arow + 32 * q;
        float4 xv = *(const float4*)(X + (size_t)(m0 + row) * KK + k0 + akq);
        float4 mv = *(const float4*)(MX + (size_t)((m0 + row) & (BB - 1)) * KK + k0 + akq);
        xv.x *= mv.x; xv.y *= mv.y; xv.z *= mv.z; xv.w *= mv.w;
        pa[q] = xv;
    }
#pragma unroll
    for (int q = 0; q < 2; q++) {
        int row = arow + 32 * q;
        pb[q] = *(const float4*)(W + (size_t)(n0 + row) * KK + k0 + akq);
    }
}

__device__ __forceinline__ void g_store_chunk(
    unsigned (*Ah)[20], unsigned (*Al)[20],
    unsigned (*Bh)[20], unsigned (*Bl)[20],
    int arow, int akq, const float4* pa, const float4* pb)
{
    const int p = akq >> 1;
#pragma unroll
    for (int q = 0; q < 4; q++) {
        int row = arow + 32 * q;
        unsigned h0, l0, h1, l1;
        splitb2(pa[q].x, pa[q].y, h0, l0);
        splitb2(pa[q].z, pa[q].w, h1, l1);
        Ah[row][p] = h0; Ah[row][p + 1] = h1;
        Al[row][p] = l0; Al[row][p + 1] = l1;
    }
#pragma unroll
    for (int q = 0; q < 2; q++) {
        int row = arow + 32 * q;
        unsigned h0, l0, h1, l1;
        splitb2(pb[q].x, pb[q].y, h0, l0);
        splitb2(pb[q].z, pb[q].w, h1, l1);
        Bh[row][p] = h0; Bh[row][p + 1] = h1;
        Bl[row][p] = l0; Bl[row][p + 1] = l1;
    }
}

// ---------------------------------------------------------------------------
// gemm_x — bf16 2-term split (hh, hl, lh), m16n8k16: half the MMAs and
// fragment LDS of the tf32 version. Register prefetch hides LDG latency.
// smem: uint stride 20 -> fragment banks (20g+tg) mod 32 cover 0..31.
// Static smem 30.7 KB (< 48 KB).
// ---------------------------------------------------------------------------
__global__ __launch_bounds__(256) void gemm_x_bf16(
    const float* __restrict__ X, const float* __restrict__ MX,
    const float* __restrict__ W, const float* __restrict__ bih,
    const float* __restrict__ bhh)
{
    __shared__ unsigned Ah[128][20], Al[128][20];
    __shared__ unsigned Bh[64][20],  Bl[64][20];

    const int m0 = blockIdx.x * 128;
    const int n0 = blockIdx.y * 64;
    const int tid = threadIdx.x;
    const int warp = tid >> 5;
    const int lane = tid & 31;
    const int g = lane >> 2;
    const int tg = lane & 3;
    const int wm = warp * 16;

    const int arow = tid >> 3;
    const int akq = (tid & 7) * 4;

    float acc[8][4];
#pragma unroll
    for (int nt = 0; nt < 8; nt++)
#pragma unroll
        for (int i = 0; i < 4; i++) acc[nt][i] = 0.0f;

    float4 pa[4], pb[2];
    g_load_chunk(X, MX, W, m0, n0, 0, arow, akq, pa, pb);
    g_store_chunk(Ah, Al, Bh, Bl, arow, akq, pa, pb);
    __syncthreads();

    for (int kc = 0; kc < 8; kc++) {
        if (kc < 7)
            g_load_chunk(X, MX, W, m0, n0, (kc + 1) * 32, arow, akq, pa, pb);

#pragma unroll
        for (int ks = 0; ks < 2; ks++) {
            const int kp = ks * 8;                // pair base of this k16 step
            unsigned ah[4], al[4];
            ah[0] = Ah[wm + g][kp + tg];
            ah[1] = Ah[wm + g + 8][kp + tg];
            ah[2] = Ah[wm + g][kp + tg + 4];
            ah[3] = Ah[wm + g + 8][kp + tg + 4];
            al[0] = Al[wm + g][kp + tg];
            al[1] = Al[wm + g + 8][kp + tg];
            al[2] = Al[wm + g][kp + tg + 4];
            al[3] = Al[wm + g + 8][kp + tg + 4];
            unsigned bh0[8], bh1[8], bl0[8], bl1[8];
#pragma unroll
            for (int nt = 0; nt < 8; nt++) {
                bh0[nt] = Bh[nt * 8 + g][kp + tg];
                bh1[nt] = Bh[nt * 8 + g][kp + tg + 4];
                bl0[nt] = Bl[nt * 8 + g][kp + tg];
                bl1[nt] = Bl[nt * 8 + g][kp + tg + 4];
            }
            // term-major: consecutive MMAs independent
#pragma unroll
            for (int nt = 0; nt < 8; nt++) mma_bf16(acc[nt], ah, bh0[nt], bh1[nt]);
#pragma unroll
            for (int nt = 0; nt < 8; nt++) mma_bf16(acc[nt], ah, bl0[nt], bl1[nt]);
#pragma unroll
            for (int nt = 0; nt < 8; nt++) mma_bf16(acc[nt], al, bh0[nt], bh1[nt]);
        }

        if (kc < 7) {
            __syncthreads();      // everyone done reading the buffer
            g_store_chunk(Ah, Al, Bh, Bl, arow, akq, pa, pb);
            __syncthreads();      // buffer ready
        }
    }

    // epilogue: add biases, store float2 pairs
#pragma unroll
    for (int nt = 0; nt < 8; nt++) {
        const int n = n0 + nt * 8 + tg * 2;
        const float bs0 = bih[n] + bhh[n];
        const float bs1 = bih[n + 1] + bhh[n + 1];
        const int m = m0 + wm + g;
        float2 r0 = make_float2(acc[nt][0] + bs0, acc[nt][1] + bs1);
        float2 r1 = make_float2(acc[nt][2] + bs0, acc[nt][3] + bs1);
        *(float2*)&g_gx[(size_t)m * GG + n] = r0;
        *(float2*)&g_gx[(size_t)(m + 8) * GG + n] = r1;
    }
}

// ---------------------------------------------------------------------------
// Grid-wide barrier, RBLK arrivals (128 CTAs co-resident: 1 CTA/SM by smem).
// ---------------------------------------------------------------------------
__device__ __forceinline__ void grid_barrier()
{
    __threadfence();
    __syncthreads();
    if (threadIdx.x == 0) {
        unsigned gen = *(volatile unsigned*)&g_gen;
        if (atomicAdd(&g_bar, 1u) == (unsigned)(RBLK - 1)) {
            g_bar = 0;
            __threadfence();
            *(volatile unsigned*)&g_gen = gen + 1;
        } else {
            while (*(volatile unsigned*)&g_gen == gen) { }
        }
    }
    __syncthreads();
}

__device__ __forceinline__ float fsig(float x) {
    return __fdividef(1.0f, 1.0f + __expf(-x));
}
__device__ __forceinline__ float ftanh(float x) {
    return __fdividef(2.0f, 1.0f + __expf(-2.0f * x)) - 1.0f;
}

// ---------------------------------------------------------------------------
// Tensor-core persistent recurrence — R15 verbatim (proven 4787us).
// ---------------------------------------------------------------------------
#define SM_WH   0
#define SM_WL   18432
#define SM_AH   36864
#define SM_AL   45184
#define SM_STG  53504
#define SM_BSZ  55680
#define SM_FLOATS 56192

__global__ __launch_bounds__(RTHR) void recurrent_tc(
    const float* __restrict__ mh, const float* __restrict__ Whh,
    const int* __restrict__ bsz, const float* __restrict__ h0,
    const float* __restrict__ c0, float* __restrict__ out)
{
    extern __shared__ float sm[];
    float* Wh = sm + SM_WH;
    float* Wl = sm + SM_WL;
    float* Ah = sm + SM_AH;    // [32][260] hm hi
    float* Al = sm + SM_AL;    // [32][260] hm lo
    float* STG = sm + SM_STG;  // [32][68] gate staging
    int* SB = (int*)(sm + SM_BSZ);

    const int bb = blockIdx.x >> 4;
    const int nb = blockIdx.x & 15;
    const int b0 = bb * 32;
    const int j0 = nb * 16;
    const int tid = threadIdx.x;
    const int warp = tid >> 5;
    const int lane = tid & 31;
    const int g = lane >> 2;
    const int tg = lane & 3;
    const int wm = (warp & 1) * 16;
    const int np = (warp >> 1) * 16;

    // one-time: split W_hh slice into Wh/Wl [kc][nloc][36]
    for (int i = tid; i < 64 * 256; i += RTHR) {
        int nloc = i >> 8;
        int k = i & 255;
        int nglob = (nloc >> 4) * 256 + j0 + (nloc & 15);
        unsigned h, l;
        split_tf32(Whh[(size_t)nglob * KK + k], h, l);
        int idx = ((k >> 5) * 64 + nloc) * 36 + (k & 31);
        Wh[idx] = __uint_as_float(h);
        Wl[idx] = __uint_as_float(l);
    }
    for (int i = tid; i < TT; i += RTHR) SB[i] = bsz[i];

    // one-time: register state
    const int jl = tid & 15;
    const int bl0 = tid >> 4;
    const int j = j0 + jl;
    float mhv[2], cc[2], hh[2];
#pragma unroll
    for (int r = 0; r < 2; r++) {
        int b = b0 + bl0 + 16 * r;
        mhv[r] = mh[b * HH + j];
        cc[r] = c0[b * HH + j];
        hh[r] = h0[b * HH + j];
        g_hm[0][b * HH + j] = hh[r] * mhv[r];
    }
    __syncthreads();
    grid_barrier();

    const int arow = tid >> 3;
    const int akq = (tid & 7) * 4;

    float gx[2][4];
#pragma unroll
    for (int r = 0; r < 2; r++) {
        const float* gp = g_gx + (size_t)(b0 + bl0 + 16 * r) * GG + j;
#pragma unroll
        for (int q = 0; q < 4; q++) gx[r][q] = __ldcg(gp + q * 256);
    }

    for (int t = 0; t < TT; t++) {
        const float* __restrict__ hmp = g_hm[t & 1];
        float* __restrict__ hmn = g_hm[(t & 1) ^ 1];

        // load hm tile and pre-split (one split per element per step)
        {
            const float* src = hmp + (size_t)(b0 + arow) * HH + akq;
#pragma unroll
            for (int q = 0; q < 8; q++) {
                float4 v = __ldcg((const float4*)(src + q * 32));
                const int kb = arow * 260 + akq + q * 32;
                unsigned h, l;
                split_tf32(v.x, h, l); Ah[kb]     = __uint_as_float(h); Al[kb]     = __uint_as_float(l);
                split_tf32(v.y, h, l); Ah[kb + 1] = __uint_as_float(h); Al[kb + 1] = __uint_as_float(l);
                split_tf32(v.z, h, l); Ah[kb + 2] = __uint_as_float(h); Al[kb + 2] = __uint_as_float(l);
                split_tf32(v.w, h, l); Ah[kb + 3] = __uint_as_float(h); Al[kb + 3] = __uint_as_float(l);
            }
        }
        __syncthreads();

        // MMA: 2 output tiles x 3 term-chains = 6 independent accumulators
        float a0h[4] = {0,0,0,0}, a0m[4] = {0,0,0,0}, a0l[4] = {0,0,0,0};
        float a1h[4] = {0,0,0,0}, a1m[4] = {0,0,0,0}, a1l[4] = {0,0,0,0};
        for (int kc = 0; kc < 8; kc++) {
#pragma unroll
            for (int ks = 0; ks < 4; ks++) {
                const int kk = ks * 8;
                const int kg = kc * 32 + kk;
                unsigned ah[4], al[4];
                ah[0] = __float_as_uint(Ah[(wm + g) * 260 + kg + tg]);
                ah[1] = __float_as_uint(Ah[(wm + g + 8) * 260 + kg + tg]);
                ah[2] = __float_as_uint(Ah[(wm + g) * 260 + kg + tg + 4]);
                ah[3] = __float_as_uint(Ah[(wm + g + 8) * 260 + kg + tg + 4]);
                al[0] = __float_as_uint(Al[(wm + g) * 260 + kg + tg]);
                al[1] = __float_as_uint(Al[(wm + g + 8) * 260 + kg + tg]);
                al[2] = __float_as_uint(Al[(wm + g) * 260 + kg + tg + 4]);
                al[3] = __float_as_uint(Al[(wm + g + 8) * 260 + kg + tg + 4]);
                const int w0 = ((kc * 64) + np + g) * 36 + kk + tg;
                const int w1 = ((kc * 64) + np + 8 + g) * 36 + kk + tg;
                unsigned b0h0 = __float_as_uint(Wh[w0]);
                unsigned b0h1 = __float_as_uint(Wh[w0 + 4]);
                unsigned b0l0 = __float_as_uint(Wl[w0]);
                unsigned b0l1 = __float_as_uint(Wl[w0 + 4]);
                unsigned b1h0 = __float_as_uint(Wh[w1]);
                unsigned b1h1 = __float_as_uint(Wh[w1 + 4]);
                unsigned b1l0 = __float_as_uint(Wl[w1]);
                unsigned b1l1 = __float_as_uint(Wl[w1 + 4]);
                mma_tf32(a0h, ah, b0h0, b0h1);
                mma_tf32(a1h, ah, b1h0, b1h1);
                mma_tf32(a0m, ah, b0l0, b0l1);
                mma_tf32(a1m, ah, b1l0, b1l1);
                mma_tf32(a0l, al, b0h0, b0h1);
                mma_tf32(a1l, al, b1h0, b1h1);
            }
        }
        float acc0[4], acc1[4];
#pragma unroll
        for (int i = 0; i < 4; i++) {
            acc0[i] = a0h[i] + a0m[i] + a0l[i];
            acc1[i] = a1h[i] + a1m[i] + a1l[i];
        }

        // stage accumulators: STG[row][nloc]
        {
            int nc0 = np + tg * 2;
            *(float2*)&STG[(wm + g) * 68 + nc0]     = make_float2(acc0[0], acc0[1]);
            *(float2*)&STG[(wm + g + 8) * 68 + nc0] = make_float2(acc0[2], acc0[3]);
            int nc1 = np + 8 + tg * 2;
            *(float2*)&STG[(wm + g) * 68 + nc1]     = make_float2(acc1[0], acc1[1]);
            *(float2*)&STG[(wm + g + 8) * 68 + nc1] = make_float2(acc1[2], acc1[3]);
        }
        __syncthreads();

        // pointwise: 2 owned cells
        const int size = SB[t];
        float o[2];
#pragma unroll
        for (int r = 0; r < 2; r++) {
            const int bl = bl0 + 16 * r;
            const int b = b0 + bl;
            float a0 = STG[bl * 68 + jl]      + gx[r][0];
            float a1 = STG[bl * 68 + 16 + jl] + gx[r][1];
            float a2 = STG[bl * 68 + 32 + jl] + gx[r][2];
            float a3 = STG[bl * 68 + 48 + jl] + gx[r][3];
            float iv = fsig(a0), fv = fsig(a1), gv = ftanh(a2), ov = fsig(a3);
            float cn = fv * cc[r] + iv * gv;
            float hn = ov * ftanh(cn);
            bool act = b < size;
            if (act) { cc[r] = cn; hh[r] = hn; }
            o[r] = act ? hn : 0.0f;
            hmn[b * HH + j] = hh[r] * mhv[r];
        }

        // prefetch gx(t+1)
        if (t + 1 < TT) {
#pragma unroll
            for (int r = 0; r < 2; r++) {
                const float* gp = g_gx + ((size_t)(t + 1) * BB + b0 + bl0 + 16 * r) * GG + j;
#pragma unroll
                for (int q = 0; q < 4; q++) gx[r][q] = __ldcg(gp + q * 256);
            }
        }

        grid_barrier();

#pragma unroll
        for (int r = 0; r < 2; r++)
            out[((size_t)t * BB + b0 + bl0 + 16 * r) * HH + j] = o[r];
    }

    // final hn, cn
    const size_t TBH = (size_t)TT * BB * HH;
#pragma unroll
    for (int r = 0; r < 2; r++) {
        int b = b0 + bl0 + 16 * r;
        out[TBH + b * HH + j] = hh[r];
        out[TBH + BB * HH + b * HH + j] = cc[r];
    }
}

// ---------------------------------------------------------------------------
extern "C" void kernel_launch(void* const* d_in, const int* in_sizes, int n_in,
                              void* d_out, int out_size)
{
    const float* X   = (const float*)d_in[0];   // [T,B,D]
    const float* h0  = (const float*)d_in[1];   // [B,H]
    const float* c0  = (const float*)d_in[2];   // [B,H]
    const float* mx  = (const float*)d_in[3];   // [B,D]
    const float* mh  = (const float*)d_in[4];   // [B,H]
    const float* Wih = (const float*)d_in[5];   // [4H,D]
    const float* Whh = (const float*)d_in[6];   // [4H,H]
    const float* bih = (const float*)d_in[7];   // [4H]
    const float* bhh = (const float*)d_in[8];   // [4H]
    const int*   bsz = (const int*)d_in[9];     // [T]
    float* out = (float*)d_out;                 // [T*B*H] ++ [B*H] ++ [B*H]

    static int smem_set = 0;
    if (!smem_set) {
        cudaFuncSetAttribute(recurrent_tc,
                             cudaFuncAttributeMaxDynamicSharedMemorySize,
                             SM_FLOATS * 4);
        smem_set = 1;
    }

    gemm_x_bf16<<<dim3((TT * BB) / 128, GG / 64), 256>>>(X, mx, Wih, bih, bhh);
    recurrent_tc<<<RBLK, RTHR, SM_FLOATS * 4>>>(mh, Whh, bsz, h0, c0, out);
}